// round 1
// baseline (speedup 1.0000x reference)
#include <cuda_runtime.h>
#include <cstdint>

// Problem constants
#define BB 16
#define HH 50
#define SS 256
#define DD 256
#define KK 32
#define SM1 255   // S-1 sliced rows

__device__ __forceinline__ unsigned long long umax64(unsigned long long a,
                                                     unsigned long long b) {
    return a > b ? a : b;
}

__global__ __launch_bounds__(256, 6)
void mr_kernel(const float* __restrict__ sel,    // (B,H,S,D)
               const float* __restrict__ txt,    // (B,H,S,D)
               const float* __restrict__ user,   // (B,1,D)
               const float* __restrict__ am,     // (B,H,S)
               const int*   __restrict__ rm,     // (B,H,S) int32
               const float* __restrict__ seg,    // (H,1,D)
               float* __restrict__ out_terms,    // (B,H*K,D)
               float* __restrict__ out_mask,     // (B,H*K)
               float* __restrict__ out_kid)      // (B,H,K) as float
{
    __shared__ float q_sh[DD];
    __shared__ float seg_sh[DD];
    __shared__ float score_sh[256];
    __shared__ unsigned long long key_sh[256];
    __shared__ unsigned long long wmax[2][8];
    __shared__ unsigned long long topkey[KK];
    __shared__ float w_sh[KK];
    __shared__ int   kid_sh[KK];
    __shared__ float qn_sh;

    const int bh   = blockIdx.x;       // b*HH + h
    const int b    = bh / HH;
    const int h    = bh % HH;
    const int tid  = threadIdx.x;
    const int wid  = tid >> 5;
    const int lane = tid & 31;

    // Stage q and seg rows into shared
    q_sh[tid]   = user[b * DD + tid];
    seg_sh[tid] = seg[h * DD + tid];
    __syncthreads();

    // ||q|| (warp 0)
    if (wid == 0) {
        float ss = 0.f;
        #pragma unroll
        for (int i = 0; i < 8; i++) {
            float v = q_sh[lane * 8 + i];
            ss += v * v;
        }
        #pragma unroll
        for (int o = 16; o > 0; o >>= 1)
            ss += __shfl_xor_sync(0xffffffffu, ss, o);
        if (lane == 0) qn_sh = fmaxf(__fsqrt_rn(ss), 1e-12f);
    }
    __syncthreads();
    const float qn = qn_sh;

    // ---------------- Phase A: cosine scores for sliced rows t = 0..254 ----
    const size_t base = (size_t)bh * SS * DD;              // element offset of (b,h,0,0)
    const float4* q4 = reinterpret_cast<const float4*>(q_sh);

    for (int t = wid; t < 256; t += 8) {
        unsigned long long key = 0ull;
        float score = 0.f;
        if (t < SM1) {
            const float4* p = reinterpret_cast<const float4*>(sel + base + (size_t)(t + 1) * DD);
            float4 a0 = p[lane];
            float4 a1 = p[lane + 32];
            float4 b0 = q4[lane];
            float4 b1 = q4[lane + 32];
            float dot = a0.x * b0.x + a0.y * b0.y + a0.z * b0.z + a0.w * b0.w
                      + a1.x * b1.x + a1.y * b1.y + a1.z * b1.z + a1.w * b1.w;
            float ss  = a0.x * a0.x + a0.y * a0.y + a0.z * a0.z + a0.w * a0.w
                      + a1.x * a1.x + a1.y * a1.y + a1.z * a1.z + a1.w * a1.w;
            #pragma unroll
            for (int o = 16; o > 0; o >>= 1) {
                dot += __shfl_xor_sync(0xffffffffu, dot, o);
                ss  += __shfl_xor_sync(0xffffffffu, ss,  o);
            }
            float sn = fmaxf(__fsqrt_rn(ss), 1e-12f);
            score = __fdiv_rn(dot, sn * qn);

            bool valid = (t < KK) || (rm[bh * SS + (t + 1)] != 0);
            if (valid) {
                unsigned u = __float_as_uint(score);
                u = (u & 0x80000000u) ? ~u : (u | 0x80000000u);   // order-preserving map
                key = ((unsigned long long)u << 32) | (unsigned long long)(0xFFFFFFFFu - (unsigned)t);
            }
        }
        if (lane == 0) {
            key_sh[t]   = key;
            score_sh[t] = score;
        }
    }
    __syncthreads();

    // ---------------- Phase B: iterative top-32 extraction -----------------
    unsigned long long mykey = key_sh[tid];
    for (int it = 0; it < KK; ++it) {
        unsigned long long k = mykey;
        #pragma unroll
        for (int o = 16; o > 0; o >>= 1)
            k = umax64(k, __shfl_xor_sync(0xffffffffu, k, o));
        if (lane == 0) wmax[it & 1][wid] = k;
        __syncthreads();
        unsigned long long win = wmax[it & 1][0];
        #pragma unroll
        for (int j = 1; j < 8; j++) win = umax64(win, wmax[it & 1][j]);
        if (mykey == win) mykey = 0ull;   // keys are unique; winner retires itself
        if (tid == 0) topkey[it] = win;
    }
    __syncthreads();

    // ---------------- Phase C: softmax over top-K (warp 0) -----------------
    if (wid == 0) {
        unsigned long long winv = topkey[lane];
        int kid = (int)(0xFFFFFFFFu - (unsigned)(winv & 0xFFFFFFFFull));
        float sc = score_sh[kid];
        float m  = __shfl_sync(0xffffffffu, sc, 0);   // topkey[0] is the max
        float e  = expf(sc - m);
        float s  = e;
        #pragma unroll
        for (int o = 16; o > 0; o >>= 1)
            s += __shfl_xor_sync(0xffffffffu, s, o);
        w_sh[lane]   = e / s;
        kid_sh[lane] = kid;
        out_kid[bh * KK + lane]  = (float)kid;
        out_mask[bh * KK + lane] = am[bh * SS + kid + 1];
    }
    __syncthreads();

    // ---------------- Phase D: gather, scale, add segment ------------------
    const float4* seg4 = reinterpret_cast<const float4*>(seg_sh);
    const float4* t4   = reinterpret_cast<const float4*>(txt + base);
    float4* o4 = reinterpret_cast<float4*>(out_terms + (size_t)bh * KK * DD);
    #pragma unroll
    for (int j = 0; j < 8; j++) {
        int idx = tid + j * 256;     // 0..2047 float4s  (= 32 rows * 64 float4)
        int k   = idx >> 6;
        int c   = idx & 63;
        float wgt = w_sh[k];
        int row   = kid_sh[k] + 1;
        float4 v  = t4[row * 64 + c];
        float4 sg = seg4[c];
        float4 o;
        o.x = v.x * wgt + sg.x;
        o.y = v.y * wgt + sg.y;
        o.z = v.z * wgt + sg.z;
        o.w = v.w * wgt + sg.w;
        o4[idx] = o;
    }
}

extern "C" void kernel_launch(void* const* d_in, const int* in_sizes, int n_in,
                              void* d_out, int out_size) {
    // metadata order: sel, txt, user_repr, news_repr(unused), his_attn_mask,
    //                 his_refined_mask(int32), segment_embedding
    const float* sel  = (const float*)d_in[0];
    const float* txt  = (const float*)d_in[1];
    const float* user = (const float*)d_in[2];
    const float* am   = (const float*)d_in[4];
    const int*   rm   = (const int*)  d_in[5];
    const float* seg  = (const float*)d_in[6];

    float* out = (float*)d_out;
    float* out_terms = out;                                       // 16*1600*256
    float* out_mask  = out + (size_t)BB * HH * KK * DD;           // +6,553,600
    float* out_kid   = out_mask + (size_t)BB * HH * KK;           // +25,600

    mr_kernel<<<BB * HH, 256>>>(sel, txt, user, am, rm, seg,
                                out_terms, out_mask, out_kid);
}

// round 2
// speedup vs baseline: 1.1668x; 1.1668x over previous
#include <cuda_runtime.h>
#include <cstdint>

#define BB 16
#define HH 50
#define SS 256
#define DD 256
#define KK 32
#define SM1 255   // S-1 sliced rows

__device__ __forceinline__ unsigned long long umax64(unsigned long long a,
                                                     unsigned long long b) {
    return a > b ? a : b;
}

__device__ __forceinline__ unsigned long long wmax64(unsigned long long k) {
    #pragma unroll
    for (int o = 16; o > 0; o >>= 1)
        k = umax64(k, __shfl_xor_sync(0xffffffffu, k, o));
    return k;
}

__global__ __launch_bounds__(256, 4)
void mr_kernel(const float* __restrict__ sel,    // (B,H,S,D)
               const float* __restrict__ txt,    // (B,H,S,D)
               const float* __restrict__ user,   // (B,1,D)
               const float* __restrict__ am,     // (B,H,S)
               const int*   __restrict__ rm,     // (B,H,S)
               const float* __restrict__ seg,    // (H,1,D)
               float* __restrict__ out_terms,    // (B,H*K,D)
               float* __restrict__ out_mask,     // (B,H*K)
               float* __restrict__ out_kid)      // (B,H,K) as float
{
    __shared__ float q_sh[DD];
    __shared__ float seg_sh[DD];
    __shared__ unsigned long long key_sh[256];
    __shared__ float w_sh[KK];
    __shared__ int   kid_sh[KK];

    const int bh   = blockIdx.x;
    const int b    = bh / HH;
    const int h    = bh % HH;
    const int tid  = threadIdx.x;
    const int wid  = tid >> 5;
    const int lane = tid & 31;

    q_sh[tid]   = user[b * DD + tid];
    seg_sh[tid] = seg[h * DD + tid];
    if (tid == 255) key_sh[255] = 0ull;   // slot never produced by phase A
    __syncthreads();

    // q in registers, once
    const float4* q4 = reinterpret_cast<const float4*>(q_sh);
    const float4 qa = q4[lane];
    const float4 qb = q4[lane + 32];

    // redundant per-warp ||q|| (no extra barrier/broadcast)
    float qss = qa.x*qa.x + qa.y*qa.y + qa.z*qa.z + qa.w*qa.w
              + qb.x*qb.x + qb.y*qb.y + qb.z*qb.z + qb.w*qb.w;
    #pragma unroll
    for (int o = 16; o > 0; o >>= 1)
        qss += __shfl_xor_sync(0xffffffffu, qss, o);
    const float qn = fmaxf(__fsqrt_rn(qss), 1e-12f);

    const size_t base = (size_t)bh * SS * DD;
    const float4* s4  = reinterpret_cast<const float4*>(sel + base + DD); // row t -> s4 + t*64

    // ---------------- Phase A: warp owns contiguous 32-row chunk -----------
    const int r0   = wid * 32;
    const int rend = (r0 + 32 < SM1) ? (r0 + 32) : SM1;

    int t = r0;
    for (; t + 4 <= rend; t += 4) {
        // validity prefetch: lane k (k<4) owns row t+k
        int rmv = 1;
        if (lane < 4) {
            int row = t + lane;
            rmv = (row < KK) ? 1 : rm[bh * SS + row + 1];
        }
        // front-batch all 8 vector loads (MLP = 8/lane)
        float4 a[4][2];
        #pragma unroll
        for (int k = 0; k < 4; k++) {
            const float4* p = s4 + (size_t)(t + k) * 64;
            a[k][0] = __ldcs(p + lane);
            a[k][1] = __ldcs(p + lane + 32);
        }
        float d[4], s[4];
        #pragma unroll
        for (int k = 0; k < 4; k++) {
            float4 x = a[k][0], y = a[k][1];
            d[k] = x.x*qa.x + x.y*qa.y + x.z*qa.z + x.w*qa.w
                 + y.x*qb.x + y.y*qb.y + y.z*qb.z + y.w*qb.w;
            s[k] = x.x*x.x + x.y*x.y + x.z*x.z + x.w*x.w
                 + y.x*y.x + y.y*y.y + y.z*y.z + y.w*y.w;
        }
        // 8 interleaved independent butterfly chains
        #pragma unroll
        for (int o = 16; o > 0; o >>= 1) {
            #pragma unroll
            for (int k = 0; k < 4; k++) {
                d[k] += __shfl_xor_sync(0xffffffffu, d[k], o);
                s[k] += __shfl_xor_sync(0xffffffffu, s[k], o);
            }
        }
        // lane k writes key for row t+k (totals live in all lanes)
        if (lane < 4) {
            float dk = d[0], sk = s[0];
            if (lane == 1)      { dk = d[1]; sk = s[1]; }
            else if (lane == 2) { dk = d[2]; sk = s[2]; }
            else if (lane == 3) { dk = d[3]; sk = s[3]; }
            float sn    = fmaxf(__fsqrt_rn(sk), 1e-12f);
            float score = __fdiv_rn(dk, sn * qn);
            unsigned long long key = 0ull;
            if (rmv) {
                unsigned u = __float_as_uint(score);
                u = (u & 0x80000000u) ? ~u : (u | 0x80000000u);
                key = ((unsigned long long)u << 32)
                    | (unsigned long long)(0xFFFFFFFFu - (unsigned)(t + lane));
            }
            key_sh[t + lane] = key;
        }
    }
    // tail rows (warp 7 only: 252..254)
    for (; t < rend; ++t) {
        const float4* p = s4 + (size_t)t * 64;
        float4 x = __ldcs(p + lane);
        float4 y = __ldcs(p + lane + 32);
        float dk = x.x*qa.x + x.y*qa.y + x.z*qa.z + x.w*qa.w
                 + y.x*qb.x + y.y*qb.y + y.z*qb.z + y.w*qb.w;
        float sk = x.x*x.x + x.y*x.y + x.z*x.z + x.w*x.w
                 + y.x*y.x + y.y*y.y + y.z*y.z + y.w*y.w;
        #pragma unroll
        for (int o = 16; o > 0; o >>= 1) {
            dk += __shfl_xor_sync(0xffffffffu, dk, o);
            sk += __shfl_xor_sync(0xffffffffu, sk, o);
        }
        if (lane == 0) {
            int rmv = (t < KK) ? 1 : rm[bh * SS + t + 1];
            float sn    = fmaxf(__fsqrt_rn(sk), 1e-12f);
            float score = __fdiv_rn(dk, sn * qn);
            unsigned long long key = 0ull;
            if (rmv) {
                unsigned u = __float_as_uint(score);
                u = (u & 0x80000000u) ? ~u : (u | 0x80000000u);
                key = ((unsigned long long)u << 32)
                    | (unsigned long long)(0xFFFFFFFFu - (unsigned)t);
            }
            key_sh[t] = key;
        }
    }
    __syncthreads();

    // ---------------- Phase B+C: single-warp top-32 + softmax --------------
    if (wid == 0) {
        unsigned long long kv[8];
        #pragma unroll
        for (int i = 0; i < 8; i++) kv[i] = key_sh[lane * 8 + i];

        // 19-CE optimal sorting network, descending (kv[0] = max)
        #define CE(i,j) { if (kv[j] > kv[i]) { unsigned long long tt_ = kv[i]; kv[i] = kv[j]; kv[j] = tt_; } }
        CE(0,1) CE(2,3) CE(4,5) CE(6,7)
        CE(0,2) CE(1,3) CE(4,6) CE(5,7)
        CE(1,2) CE(5,6)
        CE(0,4) CE(1,5) CE(2,6) CE(3,7)
        CE(2,4) CE(3,5)
        CE(1,2) CE(3,4) CE(5,6)
        #undef CE

        unsigned long long mywin = 0ull;
        #pragma unroll
        for (int it = 0; it < KK; ++it) {
            unsigned long long m = wmax64(kv[0]);
            if (kv[0] == m) {            // keys unique & nonzero for top-32
                kv[0] = kv[1]; kv[1] = kv[2]; kv[2] = kv[3]; kv[3] = kv[4];
                kv[4] = kv[5]; kv[5] = kv[6]; kv[6] = kv[7]; kv[7] = 0ull;
            }
            if (lane == it) mywin = m;
        }

        // decode score + index from key
        unsigned hi   = (unsigned)(mywin >> 32);
        unsigned orig = (hi & 0x80000000u) ? (hi & 0x7fffffffu) : ~hi;
        float score   = __uint_as_float(orig);
        int kid       = (int)(0xFFFFFFFFu - (unsigned)(mywin & 0xFFFFFFFFull));

        float mx = __shfl_sync(0xffffffffu, score, 0);  // iteration 0 = global max
        float e  = expf(score - mx);
        float sm = e;
        #pragma unroll
        for (int o = 16; o > 0; o >>= 1)
            sm += __shfl_xor_sync(0xffffffffu, sm, o);

        w_sh[lane]   = e / sm;
        kid_sh[lane] = kid;
        out_kid[bh * KK + lane]  = (float)kid;
        out_mask[bh * KK + lane] = am[bh * SS + kid + 1];
    }
    __syncthreads();

    // ---------------- Phase D: gather, scale, add segment ------------------
    const float4* seg4 = reinterpret_cast<const float4*>(seg_sh);
    const float4* t4   = reinterpret_cast<const float4*>(txt + base);
    float4* o4 = reinterpret_cast<float4*>(out_terms + (size_t)bh * KK * DD);
    #pragma unroll
    for (int j = 0; j < 8; j++) {
        int idx = tid + j * 256;       // 0..2047 float4s  (32 rows * 64 float4)
        int k   = idx >> 6;
        int c   = idx & 63;
        float wgt = w_sh[k];
        int row   = kid_sh[k] + 1;
        float4 v  = __ldcs(t4 + row * 64 + c);
        float4 sg = seg4[c];
        float4 o;
        o.x = v.x * wgt + sg.x;
        o.y = v.y * wgt + sg.y;
        o.z = v.z * wgt + sg.z;
        o.w = v.w * wgt + sg.w;
        o4[idx] = o;
    }
}

extern "C" void kernel_launch(void* const* d_in, const int* in_sizes, int n_in,
                              void* d_out, int out_size) {
    const float* sel  = (const float*)d_in[0];
    const float* txt  = (const float*)d_in[1];
    const float* user = (const float*)d_in[2];
    const float* am   = (const float*)d_in[4];
    const int*   rm   = (const int*)  d_in[5];
    const float* seg  = (const float*)d_in[6];

    float* out = (float*)d_out;
    float* out_terms = out;                               // 16*1600*256
    float* out_mask  = out + (size_t)BB * HH * KK * DD;   // +6,553,600
    float* out_kid   = out_mask + (size_t)BB * HH * KK;   // +25,600

    mr_kernel<<<BB * HH, 256>>>(sel, txt, user, am, rm, seg,
                                out_terms, out_mask, out_kid);
}

// round 3
// speedup vs baseline: 1.2064x; 1.0339x over previous
#include <cuda_runtime.h>
#include <cstdint>

#define BB 16
#define HH 50
#define SS 256
#define DD 256
#define KK 32
#define SM1 255     // S-1 sliced rows
#define NSTAGE 4    // per-warp cp.async pipeline depth

__device__ __forceinline__ unsigned long long umax64(unsigned long long a,
                                                     unsigned long long b) {
    return a > b ? a : b;
}

__device__ __forceinline__ unsigned long long wmax64(unsigned long long k) {
    #pragma unroll
    for (int o = 16; o > 0; o >>= 1)
        k = umax64(k, __shfl_xor_sync(0xffffffffu, k, o));
    return k;
}

__device__ __forceinline__ void cpa16(uint32_t dst_smem, const float* src) {
    asm volatile("cp.async.cg.shared.global [%0], [%1], 16;\n"
                 :: "r"(dst_smem), "l"(src));
}
__device__ __forceinline__ void cpa_commit() {
    asm volatile("cp.async.commit_group;\n");
}
__device__ __forceinline__ void cpa_wait3() {
    asm volatile("cp.async.wait_group 3;\n");
}

__global__ __launch_bounds__(256, 6)
void mr_kernel(const float* __restrict__ sel,    // (B,H,S,D)
               const float* __restrict__ txt,    // (B,H,S,D)
               const float* __restrict__ user,   // (B,1,D)
               const float* __restrict__ am,     // (B,H,S)
               const int*   __restrict__ rm,     // (B,H,S)
               const float* __restrict__ seg,    // (H,1,D)
               float* __restrict__ out_terms,    // (B,H*K,D)
               float* __restrict__ out_mask,     // (B,H*K)
               float* __restrict__ out_kid)      // (B,H,K) as float
{
    __shared__ float abuf[8][NSTAGE][DD];        // 32 KB: per-warp stream buffers
    __shared__ float q_sh[DD];
    __shared__ float seg_sh[DD];
    __shared__ unsigned long long key_sh[256];
    __shared__ float w_sh[KK];
    __shared__ int   kid_sh[KK];

    const int bh   = blockIdx.x;
    const int b    = bh / HH;
    const int h    = bh % HH;
    const int tid  = threadIdx.x;
    const int wid  = tid >> 5;
    const int lane = tid & 31;

    q_sh[tid]   = user[b * DD + tid];
    seg_sh[tid] = seg[h * DD + tid];
    if (tid == 255) key_sh[255] = 0ull;          // slot never produced by phase A
    __syncthreads();

    // q resident in registers
    const float4* q4 = reinterpret_cast<const float4*>(q_sh);
    const float4 qa = q4[lane];
    const float4 qb = q4[lane + 32];

    // redundant per-warp ||q||
    float qss = qa.x*qa.x + qa.y*qa.y + qa.z*qa.z + qa.w*qa.w
              + qb.x*qb.x + qb.y*qb.y + qb.z*qb.z + qb.w*qb.w;
    #pragma unroll
    for (int o = 16; o > 0; o >>= 1)
        qss += __shfl_xor_sync(0xffffffffu, qss, o);
    const float qn = fmaxf(__fsqrt_rn(qss), 1e-12f);

    const size_t base = (size_t)bh * SS * DD;
    const float* rowbase = sel + base + DD;      // sliced row t -> rowbase + t*DD

    // ---------------- Phase A: per-warp cp.async streaming -----------------
    const int r0    = wid * 32;
    const int nrows = (r0 + 32 <= SM1) ? 32 : (SM1 - r0);   // 32, warp7: 31

    // per-lane validity for this warp's rows (one coalesced load)
    int myrm = 0;
    {
        int row = r0 + lane;
        if (row < SM1) myrm = (row < KK) ? 1 : rm[bh * SS + row + 1];
    }

    const uint32_t sbase = (uint32_t)__cvta_generic_to_shared(&abuf[wid][0][0]);
    const uint32_t loff  = (uint32_t)lane * 16u;

    // prologue: fill pipeline
    #pragma unroll
    for (int s = 0; s < NSTAGE; s++) {
        if (s < nrows) {
            const float* src = rowbase + (size_t)(r0 + s) * DD;
            uint32_t dst = sbase + (uint32_t)s * (DD * 4);
            cpa16(dst + loff,       src + lane * 4);
            cpa16(dst + 512 + loff, src + 128 + lane * 4);
        }
        cpa_commit();
    }

    for (int i = 0; i < nrows; ++i) {
        cpa_wait3();                 // group i complete (own-lane data only)

        const float4* bp = reinterpret_cast<const float4*>(&abuf[wid][i & (NSTAGE-1)][0]);
        float4 x = bp[lane];
        float4 y = bp[lane + 32];
        float dk = x.x*qa.x + x.y*qa.y + x.z*qa.z + x.w*qa.w
                 + y.x*qb.x + y.y*qb.y + y.z*qb.z + y.w*qb.w;
        float sk = x.x*x.x + x.y*x.y + x.z*x.z + x.w*x.w
                 + y.x*y.x + y.y*y.y + y.z*y.z + y.w*y.w;
        #pragma unroll
        for (int o = 16; o > 0; o >>= 1) {
            dk += __shfl_xor_sync(0xffffffffu, dk, o);
            sk += __shfl_xor_sync(0xffffffffu, sk, o);
        }
        int rmv = __shfl_sync(0xffffffffu, myrm, i);
        if (lane == 0) {
            float sn    = fmaxf(__fsqrt_rn(sk), 1e-12f);
            float score = __fdiv_rn(dk, sn * qn);
            unsigned long long key = 0ull;
            if (rmv) {
                unsigned u = __float_as_uint(score);
                u = (u & 0x80000000u) ? ~u : (u | 0x80000000u);
                key = ((unsigned long long)u << 32)
                    | (unsigned long long)(0xFFFFFFFFu - (unsigned)(r0 + i));
            }
            key_sh[r0 + i] = key;
        }

        // refill slot (or empty group to keep wait_group accounting exact)
        int nxt = i + NSTAGE;
        if (nxt < nrows) {
            const float* src = rowbase + (size_t)(r0 + nxt) * DD;
            uint32_t dst = sbase + (uint32_t)(nxt & (NSTAGE-1)) * (DD * 4);
            cpa16(dst + loff,       src + lane * 4);
            cpa16(dst + 512 + loff, src + 128 + lane * 4);
        }
        cpa_commit();
    }
    __syncthreads();

    // ---------------- Phase B+C: single-warp top-32 + softmax --------------
    if (wid == 0) {
        unsigned long long kv[8];
        #pragma unroll
        for (int i = 0; i < 8; i++) kv[i] = key_sh[lane * 8 + i];

        // 19-CE optimal sorting network, descending (kv[0] = max)
        #define CE(i,j) { if (kv[j] > kv[i]) { unsigned long long tt_ = kv[i]; kv[i] = kv[j]; kv[j] = tt_; } }
        CE(0,1) CE(2,3) CE(4,5) CE(6,7)
        CE(0,2) CE(1,3) CE(4,6) CE(5,7)
        CE(1,2) CE(5,6)
        CE(0,4) CE(1,5) CE(2,6) CE(3,7)
        CE(2,4) CE(3,5)
        CE(1,2) CE(3,4) CE(5,6)
        #undef CE

        unsigned long long mywin = 0ull;
        #pragma unroll
        for (int it = 0; it < KK; ++it) {
            unsigned long long m = wmax64(kv[0]);
            if (kv[0] == m) {
                kv[0] = kv[1]; kv[1] = kv[2]; kv[2] = kv[3]; kv[3] = kv[4];
                kv[4] = kv[5]; kv[5] = kv[6]; kv[6] = kv[7]; kv[7] = 0ull;
            }
            if (lane == it) mywin = m;
        }

        unsigned hi   = (unsigned)(mywin >> 32);
        unsigned orig = (hi & 0x80000000u) ? (hi & 0x7fffffffu) : ~hi;
        float score   = __uint_as_float(orig);
        int kid       = (int)(0xFFFFFFFFu - (unsigned)(mywin & 0xFFFFFFFFull));

        float mx = __shfl_sync(0xffffffffu, score, 0);
        float e  = expf(score - mx);
        float sm = e;
        #pragma unroll
        for (int o = 16; o > 0; o >>= 1)
            sm += __shfl_xor_sync(0xffffffffu, sm, o);

        w_sh[lane]   = e / sm;
        kid_sh[lane] = kid;
        out_kid[bh * KK + lane]  = (float)kid;
        out_mask[bh * KK + lane] = am[bh * SS + kid + 1];
    }
    __syncthreads();

    // ---------------- Phase D: gather, scale, add segment ------------------
    const float4* seg4 = reinterpret_cast<const float4*>(seg_sh);
    const float4* t4   = reinterpret_cast<const float4*>(txt + base);
    float4* o4 = reinterpret_cast<float4*>(out_terms + (size_t)bh * KK * DD);
    #pragma unroll
    for (int j = 0; j < 8; j++) {
        int idx = tid + j * 256;       // 0..2047 float4s  (32 rows * 64 float4)
        int k   = idx >> 6;
        int c   = idx & 63;
        float wgt = w_sh[k];
        int row   = kid_sh[k] + 1;
        float4 v  = __ldcs(t4 + row * 64 + c);
        float4 sg = seg4[c];
        float4 o;
        o.x = v.x * wgt + sg.x;
        o.y = v.y * wgt + sg.y;
        o.z = v.z * wgt + sg.z;
        o.w = v.w * wgt + sg.w;
        o4[idx] = o;
    }
}

extern "C" void kernel_launch(void* const* d_in, const int* in_sizes, int n_in,
                              void* d_out, int out_size) {
    const float* sel  = (const float*)d_in[0];
    const float* txt  = (const float*)d_in[1];
    const float* user = (const float*)d_in[2];
    const float* am   = (const float*)d_in[4];
    const int*   rm   = (const int*)  d_in[5];
    const float* seg  = (const float*)d_in[6];

    float* out = (float*)d_out;
    float* out_terms = out;                               // 16*1600*256
    float* out_mask  = out + (size_t)BB * HH * KK * DD;   // +6,553,600
    float* out_kid   = out_mask + (size_t)BB * HH * KK;   // +25,600

    mr_kernel<<<BB * HH, 256>>>(sel, txt, user, am, rm, seg,
                                out_terms, out_mask, out_kid);
}

// round 4
// speedup vs baseline: 1.2794x; 1.0606x over previous
#include <cuda_runtime.h>
#include <cstdint>

#define BB 16
#define HH 50
#define SS 256
#define DD 256
#define KK 32
#define SM1 255     // S-1 sliced rows
#define NSTAGE 3    // per-warp cp.async ring depth

__device__ __forceinline__ void cpa16(uint32_t dst_smem, const float* src) {
    asm volatile("cp.async.cg.shared.global [%0], [%1], 16;\n"
                 :: "r"(dst_smem), "l"(src));
}
__device__ __forceinline__ void cpa_commit() {
    asm volatile("cp.async.commit_group;\n");
}
__device__ __forceinline__ void cpa_wait2() {
    asm volatile("cp.async.wait_group 2;\n");
}

__global__ __launch_bounds__(256, 8)
void mr_kernel(const float* __restrict__ sel,    // (B,H,S,D)
               const float* __restrict__ txt,    // (B,H,S,D)
               const float* __restrict__ user,   // (B,1,D)
               const float* __restrict__ am,     // (B,H,S)
               const int*   __restrict__ rm,     // (B,H,S)
               const float* __restrict__ seg,    // (H,1,D)
               float* __restrict__ out_terms,    // (B,H*K,D)
               float* __restrict__ out_mask,     // (B,H*K)
               float* __restrict__ out_kid)      // (B,H,K) as float
{
    // abuf doubles as key storage after each warp finishes streaming:
    // warp w's keys (32 x u64 = 256B) live at &abuf[w][0][0].
    __shared__ float abuf[8][NSTAGE][DD];        // 24 KB
    __shared__ float q_sh[DD];                   // 1 KB
    __shared__ float seg_sh[DD];                 // 1 KB
    __shared__ float w_sh[KK];
    __shared__ int   kid_sh[KK];

    const int bh   = blockIdx.x;
    const int b    = bh / HH;
    const int h    = bh % HH;
    const int tid  = threadIdx.x;
    const int wid  = tid >> 5;
    const int lane = tid & 31;

    q_sh[tid]   = user[b * DD + tid];
    seg_sh[tid] = seg[h * DD + tid];
    __syncthreads();

    const float4* q4 = reinterpret_cast<const float4*>(q_sh);

    // per-warp ||q|| (transient registers only)
    float qn;
    {
        float4 qa = q4[lane], qb = q4[lane + 32];
        float qss = qa.x*qa.x + qa.y*qa.y + qa.z*qa.z + qa.w*qa.w
                  + qb.x*qb.x + qb.y*qb.y + qb.z*qb.z + qb.w*qb.w;
        #pragma unroll
        for (int o = 16; o > 0; o >>= 1)
            qss += __shfl_xor_sync(0xffffffffu, qss, o);
        qn = fmaxf(__fsqrt_rn(qss), 1e-12f);
    }

    const size_t base = (size_t)bh * SS * DD;
    const float* rowbase = sel + base + DD;      // sliced row t -> rowbase + t*DD

    // ---------------- Phase A: per-warp cp.async streaming -----------------
    const int r0    = wid * 32;
    const int nrows = (r0 + 32 <= SM1) ? 32 : (SM1 - r0);   // 32, warp7: 31

    int myrm = 0;
    {
        int row = r0 + lane;
        if (row < SM1) myrm = (row < KK) ? 1 : rm[bh * SS + row + 1];
    }

    const uint32_t sbase = (uint32_t)__cvta_generic_to_shared(&abuf[wid][0][0]);
    const uint32_t loff  = (uint32_t)lane * 16u;

    #pragma unroll
    for (int s = 0; s < NSTAGE; s++) {           // nrows >= 31 > NSTAGE always
        const float* src = rowbase + (size_t)(r0 + s) * DD;
        uint32_t dst = sbase + (uint32_t)s * (DD * 4);
        cpa16(dst + loff,       src + lane * 4);
        cpa16(dst + 512 + loff, src + 128 + lane * 4);
        cpa_commit();
    }

    unsigned long long mykey = 0ull;             // lane i: key of row r0+i
    int slot = 0;
    for (int i = 0; i < nrows; ++i) {
        cpa_wait2();

        const float4* bp = reinterpret_cast<const float4*>(&abuf[wid][slot][0]);
        float4 x  = bp[lane];
        float4 y  = bp[lane + 32];
        float4 qa = q4[lane];
        float4 qb = q4[lane + 32];
        float dk = x.x*qa.x + x.y*qa.y + x.z*qa.z + x.w*qa.w
                 + y.x*qb.x + y.y*qb.y + y.z*qb.z + y.w*qb.w;
        float sk = x.x*x.x + x.y*x.y + x.z*x.z + x.w*x.w
                 + y.x*y.x + y.y*y.y + y.z*y.z + y.w*y.w;
        #pragma unroll
        for (int o = 16; o > 0; o >>= 1) {
            dk += __shfl_xor_sync(0xffffffffu, dk, o);
            sk += __shfl_xor_sync(0xffffffffu, sk, o);
        }
        int rmv = __shfl_sync(0xffffffffu, myrm, i);

        // all lanes compute the key; lane i keeps it (no lane-0 bottleneck)
        float sn    = fmaxf(__fsqrt_rn(sk), 1e-12f);
        float score = __fdiv_rn(dk, sn * qn);
        unsigned long long key = 0ull;
        if (rmv) {
            unsigned u = __float_as_uint(score);
            u = (u & 0x80000000u) ? ~u : (u | 0x80000000u);
            key = ((unsigned long long)u << 32)
                | (unsigned long long)(0xFFFFFFFFu - (unsigned)(r0 + i));
        }
        if (lane == i) mykey = key;

        int nxt = i + NSTAGE;                    // refill just-freed slot
        if (nxt < nrows) {
            const float* src = rowbase + (size_t)(r0 + nxt) * DD;
            uint32_t dst = sbase + (uint32_t)slot * (DD * 4);
            cpa16(dst + loff,       src + lane * 4);
            cpa16(dst + 512 + loff, src + 128 + lane * 4);
        }
        cpa_commit();
        if (++slot == NSTAGE) slot = 0;
    }

    // publish keys into this warp's (now dead) abuf region
    reinterpret_cast<unsigned long long*>(&abuf[wid][0][0])[lane] = mykey;
    __syncthreads();

    // ---------------- Phase B+C: single-warp top-32 (redux) + softmax ------
    if (wid == 0) {
        unsigned long long kv[8];
        #pragma unroll
        for (int j = 0; j < 8; j++) {
            int t = lane * 8 + j;
            kv[j] = reinterpret_cast<const unsigned long long*>(
                        &abuf[t >> 5][0][0])[t & 31];
        }

        // 19-CE optimal sorting network, descending (kv[0] = lane max)
        #define CE(i,j) { if (kv[j] > kv[i]) { unsigned long long tt_ = kv[i]; kv[i] = kv[j]; kv[j] = tt_; } }
        CE(0,1) CE(2,3) CE(4,5) CE(6,7)
        CE(0,2) CE(1,3) CE(4,6) CE(5,7)
        CE(1,2) CE(5,6)
        CE(0,4) CE(1,5) CE(2,6) CE(3,7)
        CE(2,4) CE(3,5)
        CE(1,2) CE(3,4) CE(5,6)
        #undef CE

        unsigned long long mywin = 0ull;
        #pragma unroll
        for (int it = 0; it < KK; ++it) {
            unsigned sur = (unsigned)(kv[0] >> 32);
            unsigned m   = __reduce_max_sync(0xffffffffu, sur);
            unsigned lo  = (sur == m) ? (unsigned)(kv[0] & 0xffffffffull) : 0u;
            unsigned c   = __reduce_max_sync(0xffffffffu, lo);
            unsigned long long win = ((unsigned long long)m << 32) | c;
            if (kv[0] == win) {
                kv[0] = kv[1]; kv[1] = kv[2]; kv[2] = kv[3]; kv[3] = kv[4];
                kv[4] = kv[5]; kv[5] = kv[6]; kv[6] = kv[7]; kv[7] = 0ull;
            }
            if (lane == it) mywin = win;
        }

        unsigned hi   = (unsigned)(mywin >> 32);
        unsigned orig = (hi & 0x80000000u) ? (hi & 0x7fffffffu) : ~hi;
        float score   = __uint_as_float(orig);
        int kid       = (int)(0xFFFFFFFFu - (unsigned)(mywin & 0xFFFFFFFFull));

        float mx = __shfl_sync(0xffffffffu, score, 0);  // it=0 is the global max
        float e  = expf(score - mx);
        float sm = e;
        #pragma unroll
        for (int o = 16; o > 0; o >>= 1)
            sm += __shfl_xor_sync(0xffffffffu, sm, o);

        w_sh[lane]   = e / sm;
        kid_sh[lane] = kid;
        out_kid[bh * KK + lane]  = (float)kid;
        out_mask[bh * KK + lane] = am[bh * SS + kid + 1];
    }
    __syncthreads();

    // ---------------- Phase D: gather, scale, add segment ------------------
    const float4* seg4 = reinterpret_cast<const float4*>(seg_sh);
    const float4* t4   = reinterpret_cast<const float4*>(txt + base);
    float4* o4 = reinterpret_cast<float4*>(out_terms + (size_t)bh * KK * DD);
    #pragma unroll
    for (int j = 0; j < 8; j++) {
        int idx = tid + j * 256;       // 0..2047 float4s  (32 rows * 64 float4)
        int k   = idx >> 6;
        int c   = idx & 63;
        float wgt = w_sh[k];
        int row   = kid_sh[k] + 1;
        float4 v  = __ldcs(t4 + row * 64 + c);
        float4 sg = seg4[c];
        float4 o;
        o.x = v.x * wgt + sg.x;
        o.y = v.y * wgt + sg.y;
        o.z = v.z * wgt + sg.z;
        o.w = v.w * wgt + sg.w;
        o4[idx] = o;
    }
}

extern "C" void kernel_launch(void* const* d_in, const int* in_sizes, int n_in,
                              void* d_out, int out_size) {
    const float* sel  = (const float*)d_in[0];
    const float* txt  = (const float*)d_in[1];
    const float* user = (const float*)d_in[2];
    const float* am   = (const float*)d_in[4];
    const int*   rm   = (const int*)  d_in[5];
    const float* seg  = (const float*)d_in[6];

    float* out = (float*)d_out;
    float* out_terms = out;                               // 16*1600*256
    float* out_mask  = out + (size_t)BB * HH * KK * DD;   // +6,553,600
    float* out_kid   = out_mask + (size_t)BB * HH * KK;   // +25,600

    mr_kernel<<<BB * HH, 256>>>(sel, txt, user, am, rm, seg,
                                out_terms, out_mask, out_kid);
}